// round 6
// baseline (speedup 1.0000x reference)
#include <cuda_runtime.h>
#include <math.h>

#define N_NODES 100000
#define N_EDGES 3200000
#define IN_DIM 512
#define HIDDEN 16
#define N_CLASSES 7
#define NBLK 391          // ceil(100000/256)

// ---------------- scratch (device globals; no allocation) ----------------
__device__ int   g_deg[N_NODES];
__device__ int   g_rowptr[N_NODES + 1];
__device__ int   g_fill[N_NODES];
__device__ int   g_adj[N_EDGES];
__device__ float g_dinv[N_NODES];
__device__ int   g_bsum[NBLK];
__device__ float g_h1[N_NODES * HIDDEN];    // after k_scale: dinv[i] * (x@W1)[i]
__device__ float g_y2[N_NODES * N_CLASSES]; // dinv[i] * (relu(...)@W2)[i]

// ---------------- packed f32x2 FMA (sm_100+) ----------------
__device__ __forceinline__ void fma2(float2& d, float2 a, float2 b) {
    asm("fma.rn.f32x2 %0, %1, %2, %0;"
        : "+l"(*reinterpret_cast<unsigned long long*>(&d))
        : "l"(*reinterpret_cast<unsigned long long*>(&a)),
          "l"(*reinterpret_cast<unsigned long long*>(&b)));
}

// ---------------- CSR build ----------------
__global__ void k_zero_deg() {
    int i = blockIdx.x * blockDim.x + threadIdx.x;
    if (i < N_NODES) g_deg[i] = 0;
}

__global__ void k_count(const int* __restrict__ ei) {
    int e = blockIdx.x * blockDim.x + threadIdx.x;
    if (e < N_EDGES) atomicAdd(&g_deg[ei[N_EDGES + e]], 1);
}

// pass 1: per-block sums of deg
__global__ void k_s1() {
    int t = threadIdx.x;
    int i = blockIdx.x * 256 + t;
    int lane = t & 31, w = t >> 5;
    int v = (i < N_NODES) ? g_deg[i] : 0;
    #pragma unroll
    for (int o = 16; o > 0; o >>= 1) v += __shfl_down_sync(0xffffffffu, v, o);
    __shared__ int ws[8];
    if (lane == 0) ws[w] = v;
    __syncthreads();
    if (t == 0) {
        int s = 0;
        #pragma unroll
        for (int k = 0; k < 8; k++) s += ws[k];
        g_bsum[blockIdx.x] = s;
    }
}

// pass 2 (merged): per-block offset reduce + local exclusive scan + prep
__global__ void k_s3() {
    int t = threadIdx.x;           // 256 threads
    int b = blockIdx.x;
    int lane = t & 31, w = t >> 5;
    __shared__ int ws[8], wsp[8];
    __shared__ int s_off;

    int partial = 0;
    for (int k = t; k < b; k += 256) partial += g_bsum[k];
    #pragma unroll
    for (int o = 16; o > 0; o >>= 1) partial += __shfl_down_sync(0xffffffffu, partial, o);
    if (lane == 0) ws[w] = partial;
    __syncthreads();
    if (t == 0) {
        int s = 0;
        #pragma unroll
        for (int k = 0; k < 8; k++) s += ws[k];
        s_off = s;
        if (b == NBLK - 1) g_rowptr[N_NODES] = s + g_bsum[NBLK - 1];
    }
    __syncthreads();

    int i = b * 256 + t;
    int v = (i < N_NODES) ? g_deg[i] : 0;
    int x = v;
    #pragma unroll
    for (int o = 1; o < 32; o <<= 1) {
        int u = __shfl_up_sync(0xffffffffu, x, o);
        if (lane >= o) x += u;
    }
    if (lane == 31) ws[w] = x;
    __syncthreads();
    if (t < 8) {
        int s = ws[t];
        #pragma unroll
        for (int o = 1; o < 8; o <<= 1) {
            int u = __shfl_up_sync(0x000000ffu, s, o);
            if (t >= o) s += u;
        }
        wsp[t] = s;
    }
    __syncthreads();
    int excl = x - v + (w > 0 ? wsp[w - 1] : 0) + s_off;
    if (i < N_NODES) {
        g_rowptr[i] = excl;
        g_fill[i] = excl;
        g_dinv[i] = rsqrtf((float)(v + 1));  // +1 self loop
    }
}

__global__ void k_fill(const int* __restrict__ ei) {
    int e = blockIdx.x * blockDim.x + threadIdx.x;
    if (e < N_EDGES) {
        int s = ei[e];
        int d = ei[N_EDGES + e];
        int p = atomicAdd(&g_fill[d], 1);
        g_adj[p] = s;
    }
}

// ---------------- GEMM1: g_h1 = x @ W1 (raw) -------------------------------
// 128 threads, BM=256 rows (rows tid and tid+128 per thread), BK=32,
// all 16 cols per thread. xs transposed with row-stride 257 (==1 mod 32):
// conflict-free scatter STS; consumer uses 2 scalar LDS.32 (consecutive
// across lanes -> conflict-free, and always 4B-aligned).
// f32x2 packed FMAs on col-pairs: 16 f32x2 per k per thread.
#define GBM 256
#define GBK 32
#define XSS 257   // row stride of xs in floats

__global__ __launch_bounds__(128) void k_gemm1(const float* __restrict__ x,
                                               const float* __restrict__ W1) {
    __shared__ float xs[GBK * XSS];       // xs[k * XSS + row]
    __shared__ float wsf[GBK * HIDDEN];   // wsf[k * 16 + j]
    int tid = threadIdx.x;                // 0..127
    int row0 = blockIdx.x * GBM;

    float2 acc0[8], acc1[8];              // rows tid, tid+128 x 8 col-pairs
    #pragma unroll
    for (int p = 0; p < 8; p++) {
        acc0[p] = make_float2(0.f, 0.f);
        acc1[p] = make_float2(0.f, 0.f);
    }

    for (int k0 = 0; k0 < IN_DIM; k0 += GBK) {
        // stage x: 256 rows x 32 k = 2048 float4, 16 per thread.
        // slot f: row = f>>3, k4 = f&7  -> fully coalesced 128B lines.
        #pragma unroll
        for (int it = 0; it < 16; it++) {
            int f = tid + it * 128;
            int r = f >> 3;
            int k4 = f & 7;
            int gr = row0 + r;
            float4 v = make_float4(0.f, 0.f, 0.f, 0.f);
            if (gr < N_NODES)
                v = *(const float4*)&x[(size_t)gr * IN_DIM + k0 + k4 * 4];
            int kb = k4 * 4;
            xs[(kb + 0) * XSS + r] = v.x;
            xs[(kb + 1) * XSS + r] = v.y;
            xs[(kb + 2) * XSS + r] = v.z;
            xs[(kb + 3) * XSS + r] = v.w;
        }
        // stage W: 32 k x 16 j = 512 floats, coalesced
        #pragma unroll
        for (int it = 0; it < 4; it++) {
            int idx = tid + it * 128;
            wsf[idx] = W1[k0 * HIDDEN + idx];
        }
        __syncthreads();

        #pragma unroll
        for (int k = 0; k < GBK; k++) {
            float x0 = xs[k * XSS + tid];          // scalar LDS, conflict-free
            float x1 = xs[k * XSS + tid + 128];    // scalar LDS, conflict-free
            float2 xa = make_float2(x0, x0);
            float2 xb = make_float2(x1, x1);
            const float* wk = &wsf[k * HIDDEN];
            float4 w0 = *(const float4*)&wk[0];
            float4 w1 = *(const float4*)&wk[4];
            float4 w2 = *(const float4*)&wk[8];
            float4 w3 = *(const float4*)&wk[12];
            float2 wp[8];
            wp[0] = make_float2(w0.x, w0.y); wp[1] = make_float2(w0.z, w0.w);
            wp[2] = make_float2(w1.x, w1.y); wp[3] = make_float2(w1.z, w1.w);
            wp[4] = make_float2(w2.x, w2.y); wp[5] = make_float2(w2.z, w2.w);
            wp[6] = make_float2(w3.x, w3.y); wp[7] = make_float2(w3.z, w3.w);
            #pragma unroll
            for (int p = 0; p < 8; p++) {
                fma2(acc0[p], xa, wp[p]);
                fma2(acc1[p], xb, wp[p]);
            }
        }
        __syncthreads();
    }

    int r0 = row0 + tid;
    if (r0 < N_NODES) {
        *(float4*)&g_h1[r0 * HIDDEN + 0]  = make_float4(acc0[0].x, acc0[0].y, acc0[1].x, acc0[1].y);
        *(float4*)&g_h1[r0 * HIDDEN + 4]  = make_float4(acc0[2].x, acc0[2].y, acc0[3].x, acc0[3].y);
        *(float4*)&g_h1[r0 * HIDDEN + 8]  = make_float4(acc0[4].x, acc0[4].y, acc0[5].x, acc0[5].y);
        *(float4*)&g_h1[r0 * HIDDEN + 12] = make_float4(acc0[6].x, acc0[6].y, acc0[7].x, acc0[7].y);
    }
    int r1 = r0 + 128;
    if (r1 < N_NODES) {
        *(float4*)&g_h1[r1 * HIDDEN + 0]  = make_float4(acc1[0].x, acc1[0].y, acc1[1].x, acc1[1].y);
        *(float4*)&g_h1[r1 * HIDDEN + 4]  = make_float4(acc1[2].x, acc1[2].y, acc1[3].x, acc1[3].y);
        *(float4*)&g_h1[r1 * HIDDEN + 8]  = make_float4(acc1[4].x, acc1[4].y, acc1[5].x, acc1[5].y);
        *(float4*)&g_h1[r1 * HIDDEN + 12] = make_float4(acc1[6].x, acc1[6].y, acc1[7].x, acc1[7].y);
    }
}

// apply dinv to h1 (float4 over N_NODES*HIDDEN), coalesced
__global__ void k_scale() {
    int f = blockIdx.x * blockDim.x + threadIdx.x;
    if (f < N_NODES * HIDDEN / 4) {
        int node = f >> 2;
        float dv = g_dinv[node];
        float4 v = ((float4*)g_h1)[f];
        v.x *= dv; v.y *= dv; v.z *= dv; v.w *= dv;
        ((float4*)g_h1)[f] = v;
    }
}

// ---------------- Layer-1 aggregation + relu + W2 GEMM fused ----------------
__global__ __launch_bounds__(256) void k_agg1(const float* __restrict__ b1,
                                              const float* __restrict__ W2) {
    __shared__ float sW2[HIDDEN * N_CLASSES];
    __shared__ float sb1[HIDDEN];
    int tid = threadIdx.x;
    if (tid < HIDDEN * N_CLASSES) sW2[tid] = W2[tid];
    if (tid < HIDDEN) sb1[tid] = b1[tid];
    __syncthreads();

    int lane = tid & 31;
    int wid = tid >> 5;
    int half = lane >> 4;
    int j = lane & 15;
    int node = (blockIdx.x * 8 + wid) * 2 + half;
    if (node >= N_NODES) return;
    unsigned mask = 0xFFFFu << (half * 16);
    int base = half * 16;

    float acc = g_h1[node * HIDDEN + j];   // self-loop term
    int pos = g_rowptr[node];
    int end = g_rowptr[node + 1];
    while (pos < end) {
        int cnt = end - pos;
        if (cnt > 16) cnt = 16;
        int src = (j < cnt) ? g_adj[pos + j] : 0;
        int i = 0;
        for (; i + 8 <= cnt; i += 8) {
            int s0 = __shfl_sync(mask, src, base + i);
            int s1 = __shfl_sync(mask, src, base + i + 1);
            int s2 = __shfl_sync(mask, src, base + i + 2);
            int s3 = __shfl_sync(mask, src, base + i + 3);
            int s4 = __shfl_sync(mask, src, base + i + 4);
            int s5 = __shfl_sync(mask, src, base + i + 5);
            int s6 = __shfl_sync(mask, src, base + i + 6);
            int s7 = __shfl_sync(mask, src, base + i + 7);
            float v0 = g_h1[s0 * HIDDEN + j];
            float v1 = g_h1[s1 * HIDDEN + j];
            float v2 = g_h1[s2 * HIDDEN + j];
            float v3 = g_h1[s3 * HIDDEN + j];
            float v4 = g_h1[s4 * HIDDEN + j];
            float v5 = g_h1[s5 * HIDDEN + j];
            float v6 = g_h1[s6 * HIDDEN + j];
            float v7 = g_h1[s7 * HIDDEN + j];
            acc += ((v0 + v1) + (v2 + v3)) + ((v4 + v5) + (v6 + v7));
        }
        for (; i < cnt; i++) {
            int s = __shfl_sync(mask, src, base + i);
            acc += g_h1[s * HIDDEN + j];
        }
        pos += cnt;
    }

    float dv = g_dinv[node];
    float y = fmaxf(dv * acc + sb1[j], 0.f);  // relu(agg + b1)

    #pragma unroll
    for (int c = 0; c < N_CLASSES; c++) {
        float t = y * sW2[j * N_CLASSES + c];
        t += __shfl_xor_sync(mask, t, 1);
        t += __shfl_xor_sync(mask, t, 2);
        t += __shfl_xor_sync(mask, t, 4);
        t += __shfl_xor_sync(mask, t, 8);
        if (j == c) g_y2[node * N_CLASSES + c] = dv * t;
    }
}

// ---------------- Layer-2 aggregation + bias + log_softmax ----------------
__global__ __launch_bounds__(256) void k_agg2(const float* __restrict__ b2,
                                              float* __restrict__ out) {
    int tid = threadIdx.x;
    int lane = tid & 31;
    int wid = tid >> 5;
    int sub = lane >> 3;            // 0..3
    int j = lane & 7;               // 0..7 (lane 7 inactive for data)
    int node = (blockIdx.x * 8 + wid) * 4 + sub;
    if (node >= N_NODES) return;
    unsigned mask = 0xFFu << (sub * 8);
    int base = sub * 8;
    int jr = (j < N_CLASSES) ? j : 0;

    float acc = (j < N_CLASSES) ? g_y2[node * N_CLASSES + j] : 0.f;
    int pos = g_rowptr[node];
    int end = g_rowptr[node + 1];
    while (pos < end) {
        int cnt = end - pos;
        if (cnt > 8) cnt = 8;
        int src = (j < cnt) ? g_adj[pos + j] : 0;
        int i = 0;
        for (; i + 4 <= cnt; i += 4) {
            int s0 = __shfl_sync(mask, src, base + i);
            int s1 = __shfl_sync(mask, src, base + i + 1);
            int s2 = __shfl_sync(mask, src, base + i + 2);
            int s3 = __shfl_sync(mask, src, base + i + 3);
            float v0 = g_y2[s0 * N_CLASSES + jr];
            float v1 = g_y2[s1 * N_CLASSES + jr];
            float v2 = g_y2[s2 * N_CLASSES + jr];
            float v3 = g_y2[s3 * N_CLASSES + jr];
            acc += (v0 + v1) + (v2 + v3);
        }
        for (; i < cnt; i++) {
            int s = __shfl_sync(mask, src, base + i);
            acc += g_y2[s * N_CLASSES + jr];
        }
        pos += cnt;
    }

    float dv = g_dinv[node];
    float o = dv * acc + ((j < N_CLASSES) ? __ldg(&b2[jr]) : 0.f);

    float m = (j < N_CLASSES) ? o : -1e30f;
    m = fmaxf(m, __shfl_xor_sync(mask, m, 1));
    m = fmaxf(m, __shfl_xor_sync(mask, m, 2));
    m = fmaxf(m, __shfl_xor_sync(mask, m, 4));
    float e = (j < N_CLASSES) ? expf(o - m) : 0.f;
    float s = e;
    s += __shfl_xor_sync(mask, s, 1);
    s += __shfl_xor_sync(mask, s, 2);
    s += __shfl_xor_sync(mask, s, 4);
    float ls = logf(s);
    if (j < N_CLASSES) out[node * N_CLASSES + j] = o - m - ls;
}

// ---------------- launch ----------------
extern "C" void kernel_launch(void* const* d_in, const int* in_sizes, int n_in,
                              void* d_out, int out_size) {
    const float* x  = (const float*)d_in[0];
    const int*   ei = (const int*)d_in[1];
    const float* W1 = (const float*)d_in[2];
    const float* b1 = (const float*)d_in[3];
    const float* W2 = (const float*)d_in[4];
    const float* b2 = (const float*)d_in[5];
    float* out = (float*)d_out;

    const int TB = 256;
    int gridN = (N_NODES + TB - 1) / TB;          // 391
    int gridE = (N_EDGES + TB - 1) / TB;
    int gridG = (N_NODES + GBM - 1) / GBM;        // 391
    int gridS = (N_NODES * HIDDEN / 4 + TB - 1) / TB;

    k_zero_deg<<<gridN, TB>>>();                  // 0
    k_count<<<gridE, TB>>>(ei);                   // 1
    k_s1<<<NBLK, 256>>>();                        // 2
    k_gemm1<<<gridG, 128>>>(x, W1);               // 3 <- profiled slot
    k_s3<<<NBLK, 256>>>();                        // 4
    k_fill<<<gridE, TB>>>(ei);                    // 5
    k_scale<<<gridS, TB>>>();                     // 6

    int grid1 = (N_NODES + 16 - 1) / 16;
    k_agg1<<<grid1, 256>>>(b1, W2);               // 7

    int grid2 = (N_NODES + 32 - 1) / 32;
    k_agg2<<<grid2, 256>>>(b2, out);              // 8
}

// round 7
// speedup vs baseline: 1.0715x; 1.0715x over previous
#include <cuda_runtime.h>
#include <math.h>

#define N_NODES 100000
#define N_EDGES 3200000
#define IN_DIM 512
#define HIDDEN 16
#define N_CLASSES 7
#define NBLK 391          // ceil(100000/256)

// ---------------- scratch (device globals; no allocation) ----------------
__device__ int   g_deg[N_NODES];
__device__ int   g_rowptr[N_NODES + 1];
__device__ int   g_fill[N_NODES];
__device__ int   g_adj[N_EDGES];
__device__ float g_dinv[N_NODES];
__device__ int   g_bsum[NBLK];
__device__ float g_h1[N_NODES * HIDDEN];    // after k_scale: dinv[i] * (x@W1)[i]
__device__ float g_y2[N_NODES * N_CLASSES]; // dinv[i] * (relu(...)@W2)[i]

// ---------------- CSR build ----------------
__global__ void k_zero_deg() {
    int i = blockIdx.x * blockDim.x + threadIdx.x;
    if (i < N_NODES) g_deg[i] = 0;
}

__global__ void k_count(const int* __restrict__ ei) {
    int e = blockIdx.x * blockDim.x + threadIdx.x;
    if (e < N_EDGES) atomicAdd(&g_deg[ei[N_EDGES + e]], 1);
}

// pass 1: per-block sums of deg
__global__ void k_s1() {
    int t = threadIdx.x;
    int i = blockIdx.x * 256 + t;
    int lane = t & 31, w = t >> 5;
    int v = (i < N_NODES) ? g_deg[i] : 0;
    #pragma unroll
    for (int o = 16; o > 0; o >>= 1) v += __shfl_down_sync(0xffffffffu, v, o);
    __shared__ int ws[8];
    if (lane == 0) ws[w] = v;
    __syncthreads();
    if (t == 0) {
        int s = 0;
        #pragma unroll
        for (int k = 0; k < 8; k++) s += ws[k];
        g_bsum[blockIdx.x] = s;
    }
}

// pass 2 (merged): per-block offset reduce + local exclusive scan + prep
__global__ void k_s3() {
    int t = threadIdx.x;           // 256 threads
    int b = blockIdx.x;
    int lane = t & 31, w = t >> 5;
    __shared__ int ws[8], wsp[8];
    __shared__ int s_off;

    int partial = 0;
    for (int k = t; k < b; k += 256) partial += g_bsum[k];
    #pragma unroll
    for (int o = 16; o > 0; o >>= 1) partial += __shfl_down_sync(0xffffffffu, partial, o);
    if (lane == 0) ws[w] = partial;
    __syncthreads();
    if (t == 0) {
        int s = 0;
        #pragma unroll
        for (int k = 0; k < 8; k++) s += ws[k];
        s_off = s;
        if (b == NBLK - 1) g_rowptr[N_NODES] = s + g_bsum[NBLK - 1];
    }
    __syncthreads();

    int i = b * 256 + t;
    int v = (i < N_NODES) ? g_deg[i] : 0;
    int x = v;
    #pragma unroll
    for (int o = 1; o < 32; o <<= 1) {
        int u = __shfl_up_sync(0xffffffffu, x, o);
        if (lane >= o) x += u;
    }
    if (lane == 31) ws[w] = x;
    __syncthreads();
    if (t < 8) {
        int s = ws[t];
        #pragma unroll
        for (int o = 1; o < 8; o <<= 1) {
            int u = __shfl_up_sync(0x000000ffu, s, o);
            if (t >= o) s += u;
        }
        wsp[t] = s;
    }
    __syncthreads();
    int excl = x - v + (w > 0 ? wsp[w - 1] : 0) + s_off;
    if (i < N_NODES) {
        g_rowptr[i] = excl;
        g_fill[i] = excl;
        g_dinv[i] = rsqrtf((float)(v + 1));  // +1 self loop
    }
}

__global__ void k_fill(const int* __restrict__ ei) {
    int e = blockIdx.x * blockDim.x + threadIdx.x;
    if (e < N_EDGES) {
        int s = ei[e];
        int d = ei[N_EDGES + e];
        int p = atomicAdd(&g_fill[d], 1);
        g_adj[p] = s;
    }
}

// ---------------- GEMM1: g_h1 = x @ W1 (raw; dinv via k_scale) -------------
// 256 threads, thread t = row (row0+t), all 16 cols (16 fp32 accumulators).
// x staged ROW-MAJOR with pitch 36 floats:
//   - staging STS.128: quarter-warp (8 lanes) covers banks 0..31 exactly once
//   - consumer LDS.128 xs[t*36 + 4*k4]: lane bank bases 36*l mod 32 cover all
//     banks once per phase -> conflict-free
// Per warp per 4k: 64 FMA instr vs 20 L1 wavefronts -> FMA-issue bound.
#define GBM 256
#define GBK 32
#define XP 36     // row pitch in floats

__global__ __launch_bounds__(256) void k_gemm1(const float* __restrict__ x,
                                               const float* __restrict__ W1) {
    __shared__ float xs[GBM * XP];        // 36 KB
    __shared__ float wsf[GBK * HIDDEN];   // 2 KB: wsf[k*16 + j]
    int tid = threadIdx.x;
    int row0 = blockIdx.x * GBM;

    float acc[16];
    #pragma unroll
    for (int j = 0; j < 16; j++) acc[j] = 0.f;

    for (int k0 = 0; k0 < IN_DIM; k0 += GBK) {
        // stage x: 256 rows x 32 k = 2048 float4, 8 per thread, coalesced
        #pragma unroll
        for (int it = 0; it < 8; it++) {
            int f = tid + it * 256;
            int r = f >> 3;             // 0..255
            int k4 = f & 7;             // 0..7
            int gr = row0 + r;
            float4 v = make_float4(0.f, 0.f, 0.f, 0.f);
            if (gr < N_NODES)
                v = *(const float4*)&x[(size_t)gr * IN_DIM + k0 + k4 * 4];
            *(float4*)&xs[r * XP + k4 * 4] = v;
        }
        // stage W: 32 k x 16 j = 512 floats, 2 per thread, coalesced
        wsf[tid]       = W1[k0 * HIDDEN + tid];
        wsf[tid + 256] = W1[k0 * HIDDEN + tid + 256];
        __syncthreads();

        #pragma unroll
        for (int k4 = 0; k4 < 8; k4++) {
            float4 xv = *(const float4*)&xs[tid * XP + k4 * 4];
            #pragma unroll
            for (int kk = 0; kk < 4; kk++) {
                float xk = (kk == 0) ? xv.x : (kk == 1) ? xv.y
                         : (kk == 2) ? xv.z : xv.w;
                const float* wk = &wsf[(k4 * 4 + kk) * HIDDEN];
                float4 w0 = *(const float4*)&wk[0];
                float4 w1 = *(const float4*)&wk[4];
                float4 w2 = *(const float4*)&wk[8];
                float4 w3 = *(const float4*)&wk[12];
                acc[0]  += xk * w0.x; acc[1]  += xk * w0.y;
                acc[2]  += xk * w0.z; acc[3]  += xk * w0.w;
                acc[4]  += xk * w1.x; acc[5]  += xk * w1.y;
                acc[6]  += xk * w1.z; acc[7]  += xk * w1.w;
                acc[8]  += xk * w2.x; acc[9]  += xk * w2.y;
                acc[10] += xk * w2.z; acc[11] += xk * w2.w;
                acc[12] += xk * w3.x; acc[13] += xk * w3.y;
                acc[14] += xk * w3.z; acc[15] += xk * w3.w;
            }
        }
        __syncthreads();
    }

    int r = row0 + tid;
    if (r < N_NODES) {
        *(float4*)&g_h1[r * HIDDEN + 0]  = make_float4(acc[0],  acc[1],  acc[2],  acc[3]);
        *(float4*)&g_h1[r * HIDDEN + 4]  = make_float4(acc[4],  acc[5],  acc[6],  acc[7]);
        *(float4*)&g_h1[r * HIDDEN + 8]  = make_float4(acc[8],  acc[9],  acc[10], acc[11]);
        *(float4*)&g_h1[r * HIDDEN + 12] = make_float4(acc[12], acc[13], acc[14], acc[15]);
    }
}

// apply dinv to h1 (float4 over N_NODES*HIDDEN), coalesced
__global__ void k_scale() {
    int f = blockIdx.x * blockDim.x + threadIdx.x;
    if (f < N_NODES * HIDDEN / 4) {
        int node = f >> 2;
        float dv = g_dinv[node];
        float4 v = ((float4*)g_h1)[f];
        v.x *= dv; v.y *= dv; v.z *= dv; v.w *= dv;
        ((float4*)g_h1)[f] = v;
    }
}

// ---------------- Layer-1 aggregation + relu + W2 GEMM fused ----------------
__global__ __launch_bounds__(256) void k_agg1(const float* __restrict__ b1,
                                              const float* __restrict__ W2) {
    __shared__ float sW2[HIDDEN * N_CLASSES];
    __shared__ float sb1[HIDDEN];
    int tid = threadIdx.x;
    if (tid < HIDDEN * N_CLASSES) sW2[tid] = W2[tid];
    if (tid < HIDDEN) sb1[tid] = b1[tid];
    __syncthreads();

    int lane = tid & 31;
    int wid = tid >> 5;
    int half = lane >> 4;
    int j = lane & 15;
    int node = (blockIdx.x * 8 + wid) * 2 + half;
    if (node >= N_NODES) return;
    unsigned mask = 0xFFFFu << (half * 16);
    int base = half * 16;

    float acc = g_h1[node * HIDDEN + j];   // self-loop term
    int pos = g_rowptr[node];
    int end = g_rowptr[node + 1];
    while (pos < end) {
        int cnt = end - pos;
        if (cnt > 16) cnt = 16;
        int src = (j < cnt) ? g_adj[pos + j] : 0;
        int i = 0;
        for (; i + 8 <= cnt; i += 8) {
            int s0 = __shfl_sync(mask, src, base + i);
            int s1 = __shfl_sync(mask, src, base + i + 1);
            int s2 = __shfl_sync(mask, src, base + i + 2);
            int s3 = __shfl_sync(mask, src, base + i + 3);
            int s4 = __shfl_sync(mask, src, base + i + 4);
            int s5 = __shfl_sync(mask, src, base + i + 5);
            int s6 = __shfl_sync(mask, src, base + i + 6);
            int s7 = __shfl_sync(mask, src, base + i + 7);
            float v0 = g_h1[s0 * HIDDEN + j];
            float v1 = g_h1[s1 * HIDDEN + j];
            float v2 = g_h1[s2 * HIDDEN + j];
            float v3 = g_h1[s3 * HIDDEN + j];
            float v4 = g_h1[s4 * HIDDEN + j];
            float v5 = g_h1[s5 * HIDDEN + j];
            float v6 = g_h1[s6 * HIDDEN + j];
            float v7 = g_h1[s7 * HIDDEN + j];
            acc += ((v0 + v1) + (v2 + v3)) + ((v4 + v5) + (v6 + v7));
        }
        for (; i < cnt; i++) {
            int s = __shfl_sync(mask, src, base + i);
            acc += g_h1[s * HIDDEN + j];
        }
        pos += cnt;
    }

    float dv = g_dinv[node];
    float y = fmaxf(dv * acc + sb1[j], 0.f);  // relu(agg + b1)

    #pragma unroll
    for (int c = 0; c < N_CLASSES; c++) {
        float t = y * sW2[j * N_CLASSES + c];
        t += __shfl_xor_sync(mask, t, 1);
        t += __shfl_xor_sync(mask, t, 2);
        t += __shfl_xor_sync(mask, t, 4);
        t += __shfl_xor_sync(mask, t, 8);
        if (j == c) g_y2[node * N_CLASSES + c] = dv * t;
    }
}

// ---------------- Layer-2 aggregation + bias + log_softmax ----------------
__global__ __launch_bounds__(256) void k_agg2(const float* __restrict__ b2,
                                              float* __restrict__ out) {
    int tid = threadIdx.x;
    int lane = tid & 31;
    int wid = tid >> 5;
    int sub = lane >> 3;            // 0..3
    int j = lane & 7;               // 0..7 (lane 7 inactive for data)
    int node = (blockIdx.x * 8 + wid) * 4 + sub;
    if (node >= N_NODES) return;
    unsigned mask = 0xFFu << (sub * 8);
    int base = sub * 8;
    int jr = (j < N_CLASSES) ? j : 0;

    float acc = (j < N_CLASSES) ? g_y2[node * N_CLASSES + j] : 0.f;
    int pos = g_rowptr[node];
    int end = g_rowptr[node + 1];
    while (pos < end) {
        int cnt = end - pos;
        if (cnt > 8) cnt = 8;
        int src = (j < cnt) ? g_adj[pos + j] : 0;
        int i = 0;
        for (; i + 4 <= cnt; i += 4) {
            int s0 = __shfl_sync(mask, src, base + i);
            int s1 = __shfl_sync(mask, src, base + i + 1);
            int s2 = __shfl_sync(mask, src, base + i + 2);
            int s3 = __shfl_sync(mask, src, base + i + 3);
            float v0 = g_y2[s0 * N_CLASSES + jr];
            float v1 = g_y2[s1 * N_CLASSES + jr];
            float v2 = g_y2[s2 * N_CLASSES + jr];
            float v3 = g_y2[s3 * N_CLASSES + jr];
            acc += (v0 + v1) + (v2 + v3);
        }
        for (; i < cnt; i++) {
            int s = __shfl_sync(mask, src, base + i);
            acc += g_y2[s * N_CLASSES + jr];
        }
        pos += cnt;
    }

    float dv = g_dinv[node];
    float o = dv * acc + ((j < N_CLASSES) ? __ldg(&b2[jr]) : 0.f);

    float m = (j < N_CLASSES) ? o : -1e30f;
    m = fmaxf(m, __shfl_xor_sync(mask, m, 1));
    m = fmaxf(m, __shfl_xor_sync(mask, m, 2));
    m = fmaxf(m, __shfl_xor_sync(mask, m, 4));
    float e = (j < N_CLASSES) ? expf(o - m) : 0.f;
    float s = e;
    s += __shfl_xor_sync(mask, s, 1);
    s += __shfl_xor_sync(mask, s, 2);
    s += __shfl_xor_sync(mask, s, 4);
    float ls = logf(s);
    if (j < N_CLASSES) out[node * N_CLASSES + j] = o - m - ls;
}

// ---------------- launch ----------------
extern "C" void kernel_launch(void* const* d_in, const int* in_sizes, int n_in,
                              void* d_out, int out_size) {
    const float* x  = (const float*)d_in[0];
    const int*   ei = (const int*)d_in[1];
    const float* W1 = (const float*)d_in[2];
    const float* b1 = (const float*)d_in[3];
    const float* W2 = (const float*)d_in[4];
    const float* b2 = (const float*)d_in[5];
    float* out = (float*)d_out;

    const int TB = 256;
    int gridN = (N_NODES + TB - 1) / TB;          // 391
    int gridE = (N_EDGES + TB - 1) / TB;
    int gridG = (N_NODES + GBM - 1) / GBM;        // 391
    int gridS = (N_NODES * HIDDEN / 4 + TB - 1) / TB;

    k_zero_deg<<<gridN, TB>>>();                  // 0
    k_count<<<gridE, TB>>>(ei);                   // 1
    k_s1<<<NBLK, 256>>>();                        // 2
    k_gemm1<<<gridG, 256>>>(x, W1);               // 3 <- profiled slot
    k_s3<<<NBLK, 256>>>();                        // 4
    k_fill<<<gridE, TB>>>(ei);                    // 5
    k_scale<<<gridS, TB>>>();                     // 6

    int grid1 = (N_NODES + 16 - 1) / 16;
    k_agg1<<<grid1, 256>>>(b1, W2);               // 7

    int grid2 = (N_NODES + 32 - 1) / 32;
    k_agg2<<<grid2, 256>>>(b2, out);              // 8
}

// round 8
// speedup vs baseline: 1.1697x; 1.0916x over previous
#include <cuda_runtime.h>
#include <math.h>
#include <stdint.h>

#define N_NODES 100000
#define N_EDGES 3200000
#define IN_DIM 512
#define HIDDEN 16
#define N_CLASSES 7
#define NBLK 391          // ceil(100000/256)

// ---------------- scratch (device globals; no allocation) ----------------
__device__ int   g_deg[N_NODES];
__device__ int   g_rowptr[N_NODES + 1];
__device__ int   g_fill[N_NODES];
__device__ int   g_adj[N_EDGES];
__device__ float g_dinv[N_NODES];
__device__ int   g_bsum[NBLK];
__device__ float g_h1[N_NODES * HIDDEN];    // after k_scale: dinv[i] * (x@W1)[i]
__device__ float g_y2[N_NODES * N_CLASSES]; // dinv[i] * (relu(...)@W2)[i]

// ---------------- CSR build ----------------
__global__ void k_zero_deg() {
    int i = blockIdx.x * blockDim.x + threadIdx.x;
    if (i < N_NODES) g_deg[i] = 0;
}

__global__ void k_count(const int* __restrict__ ei) {
    int e = blockIdx.x * blockDim.x + threadIdx.x;
    if (e < N_EDGES) atomicAdd(&g_deg[ei[N_EDGES + e]], 1);
}

// pass 1: per-block sums of deg
__global__ void k_s1() {
    int t = threadIdx.x;
    int i = blockIdx.x * 256 + t;
    int lane = t & 31, w = t >> 5;
    int v = (i < N_NODES) ? g_deg[i] : 0;
    #pragma unroll
    for (int o = 16; o > 0; o >>= 1) v += __shfl_down_sync(0xffffffffu, v, o);
    __shared__ int ws[8];
    if (lane == 0) ws[w] = v;
    __syncthreads();
    if (t == 0) {
        int s = 0;
        #pragma unroll
        for (int k = 0; k < 8; k++) s += ws[k];
        g_bsum[blockIdx.x] = s;
    }
}

// pass 2 (merged): per-block offset reduce + local exclusive scan + prep
__global__ void k_s3() {
    int t = threadIdx.x;           // 256 threads
    int b = blockIdx.x;
    int lane = t & 31, w = t >> 5;
    __shared__ int ws[8], wsp[8];
    __shared__ int s_off;

    int partial = 0;
    for (int k = t; k < b; k += 256) partial += g_bsum[k];
    #pragma unroll
    for (int o = 16; o > 0; o >>= 1) partial += __shfl_down_sync(0xffffffffu, partial, o);
    if (lane == 0) ws[w] = partial;
    __syncthreads();
    if (t == 0) {
        int s = 0;
        #pragma unroll
        for (int k = 0; k < 8; k++) s += ws[k];
        s_off = s;
        if (b == NBLK - 1) g_rowptr[N_NODES] = s + g_bsum[NBLK - 1];
    }
    __syncthreads();

    int i = b * 256 + t;
    int v = (i < N_NODES) ? g_deg[i] : 0;
    int x = v;
    #pragma unroll
    for (int o = 1; o < 32; o <<= 1) {
        int u = __shfl_up_sync(0xffffffffu, x, o);
        if (lane >= o) x += u;
    }
    if (lane == 31) ws[w] = x;
    __syncthreads();
    if (t < 8) {
        int s = ws[t];
        #pragma unroll
        for (int o = 1; o < 8; o <<= 1) {
            int u = __shfl_up_sync(0x000000ffu, s, o);
            if (t >= o) s += u;
        }
        wsp[t] = s;
    }
    __syncthreads();
    int excl = x - v + (w > 0 ? wsp[w - 1] : 0) + s_off;
    if (i < N_NODES) {
        g_rowptr[i] = excl;
        g_fill[i] = excl;
        g_dinv[i] = rsqrtf((float)(v + 1));  // +1 self loop
    }
}

__global__ void k_fill(const int* __restrict__ ei) {
    int e = blockIdx.x * blockDim.x + threadIdx.x;
    if (e < N_EDGES) {
        int s = ei[e];
        int d = ei[N_EDGES + e];
        int p = atomicAdd(&g_fill[d], 1);
        g_adj[p] = s;
    }
}

// ---------------- tf32 helpers ----------------
__device__ __forceinline__ void split_tf32(float v, uint32_t& hi, uint32_t& lo) {
    uint32_t h;
    asm("cvt.rna.tf32.f32 %0, %1;" : "=r"(h) : "f"(v));
    float lf = v - __uint_as_float(h);
    uint32_t l;
    asm("cvt.rna.tf32.f32 %0, %1;" : "=r"(l) : "f"(lf));
    hi = h; lo = l;
}

__device__ __forceinline__ void mma_tf32(float* d, const uint32_t* a, const uint32_t* b) {
    asm("mma.sync.aligned.m16n8k8.row.col.f32.tf32.tf32.f32 "
        "{%0,%1,%2,%3}, {%4,%5,%6,%7}, {%8,%9}, {%0,%1,%2,%3};"
        : "+f"(d[0]), "+f"(d[1]), "+f"(d[2]), "+f"(d[3])
        : "r"(a[0]), "r"(a[1]), "r"(a[2]), "r"(a[3]), "r"(b[0]), "r"(b[1]));
}

// ---------------- GEMM1: g_h1 = x @ W1 (raw; dinv via k_scale) -------------
// Tensor-core tf32 with 3xTF32 precision recovery.
// 256 threads = 8 warps; warp w handles rows [16w,16w+16) of a 128-row tile,
// all 16 cols (2 n8 MMA tiles). BK=32 (4 k8 steps per tile).
// x staged row-major pitch 36 (A-frag scalar LDS banks 4g+t+8kk: conflict-free).
// W staged per k-tile (32x16 = 2KB).
#define TBM 128
#define TBK 32
#define XP 36

__global__ __launch_bounds__(256) void k_gemm1(const float* __restrict__ x,
                                               const float* __restrict__ W1) {
    __shared__ float xs[TBM * XP];       // 18 KB
    __shared__ float sw[TBK * HIDDEN];   // 2 KB
    int tid = threadIdx.x;
    int lane = tid & 31;
    int w = tid >> 5;                    // warp 0..7
    int g = lane >> 2;                   // 0..7
    int t = lane & 3;                    // 0..3
    int row0 = blockIdx.x * TBM;

    float acc[2][4] = {};                // 2 n-tiles x 4 accum regs

    for (int k0 = 0; k0 < IN_DIM; k0 += TBK) {
        // stage x tile: 128 rows x 32 k = 1024 float4, 4 per thread, coalesced
        #pragma unroll
        for (int it = 0; it < 4; it++) {
            int f = tid + it * 256;
            int r = f >> 3;
            int k4 = f & 7;
            int gr = row0 + r;
            float4 v = make_float4(0.f, 0.f, 0.f, 0.f);
            if (gr < N_NODES)
                v = *(const float4*)&x[(size_t)gr * IN_DIM + k0 + k4 * 4];
            *(float4*)&xs[r * XP + k4 * 4] = v;
        }
        // stage W tile: 32 k x 16 j = 512 floats
        sw[tid]       = W1[k0 * HIDDEN + tid];
        sw[tid + 256] = W1[k0 * HIDDEN + tid + 256];
        __syncthreads();

        #pragma unroll
        for (int kk = 0; kk < 4; kk++) {
            int kb = kk * 8;
            int ra = (16 * w + g) * XP + kb + t;
            int rb = (16 * w + g + 8) * XP + kb + t;
            float a0f = xs[ra];
            float a1f = xs[rb];
            float a2f = xs[ra + 4];
            float a3f = xs[rb + 4];
            uint32_t ah[4], al[4];
            split_tf32(a0f, ah[0], al[0]);
            split_tf32(a1f, ah[1], al[1]);
            split_tf32(a2f, ah[2], al[2]);
            split_tf32(a3f, ah[3], al[3]);

            #pragma unroll
            for (int nt = 0; nt < 2; nt++) {
                int n0 = nt * 8;
                float b0f = sw[(kb + t) * HIDDEN + n0 + g];
                float b1f = sw[(kb + t + 4) * HIDDEN + n0 + g];
                uint32_t bh[2], bl[2];
                split_tf32(b0f, bh[0], bl[0]);
                split_tf32(b1f, bh[1], bl[1]);
                mma_tf32(acc[nt], ah, bh);   // hi*hi
                mma_tf32(acc[nt], al, bh);   // lo*hi
                mma_tf32(acc[nt], ah, bl);   // hi*lo
            }
        }
        __syncthreads();
    }

    // epilogue: lane (g,t) owns D[g][2t],D[g][2t+1] (rows 16w+g) and
    // D[g+8][2t..] (rows 16w+g+8), per n-tile.
    int row_a = row0 + 16 * w + g;
    int row_b = row_a + 8;
    #pragma unroll
    for (int nt = 0; nt < 2; nt++) {
        int c = nt * 8 + 2 * t;
        if (row_a < N_NODES)
            *(float2*)&g_h1[row_a * HIDDEN + c] = make_float2(acc[nt][0], acc[nt][1]);
        if (row_b < N_NODES)
            *(float2*)&g_h1[row_b * HIDDEN + c] = make_float2(acc[nt][2], acc[nt][3]);
    }
}

// apply dinv to h1 (float4 over N_NODES*HIDDEN), coalesced
__global__ void k_scale() {
    int f = blockIdx.x * blockDim.x + threadIdx.x;
    if (f < N_NODES * HIDDEN / 4) {
        int node = f >> 2;
        float dv = g_dinv[node];
        float4 v = ((float4*)g_h1)[f];
        v.x *= dv; v.y *= dv; v.z *= dv; v.w *= dv;
        ((float4*)g_h1)[f] = v;
    }
}

// ---------------- Layer-1 aggregation + relu + W2 GEMM fused ----------------
__global__ __launch_bounds__(256) void k_agg1(const float* __restrict__ b1,
                                              const float* __restrict__ W2) {
    __shared__ float sW2[HIDDEN * N_CLASSES];
    __shared__ float sb1[HIDDEN];
    int tid = threadIdx.x;
    if (tid < HIDDEN * N_CLASSES) sW2[tid] = W2[tid];
    if (tid < HIDDEN) sb1[tid] = b1[tid];
    __syncthreads();

    int lane = tid & 31;
    int wid = tid >> 5;
    int half = lane >> 4;
    int j = lane & 15;
    int node = (blockIdx.x * 8 + wid) * 2 + half;
    if (node >= N_NODES) return;
    unsigned mask = 0xFFFFu << (half * 16);
    int base = half * 16;

    float acc = g_h1[node * HIDDEN + j];   // self-loop term
    int pos = g_rowptr[node];
    int end = g_rowptr[node + 1];
    while (pos < end) {
        int cnt = end - pos;
        if (cnt > 16) cnt = 16;
        int src = (j < cnt) ? g_adj[pos + j] : 0;
        int i = 0;
        for (; i + 8 <= cnt; i += 8) {
            int s0 = __shfl_sync(mask, src, base + i);
            int s1 = __shfl_sync(mask, src, base + i + 1);
            int s2 = __shfl_sync(mask, src, base + i + 2);
            int s3 = __shfl_sync(mask, src, base + i + 3);
            int s4 = __shfl_sync(mask, src, base + i + 4);
            int s5 = __shfl_sync(mask, src, base + i + 5);
            int s6 = __shfl_sync(mask, src, base + i + 6);
            int s7 = __shfl_sync(mask, src, base + i + 7);
            float v0 = g_h1[s0 * HIDDEN + j];
            float v1 = g_h1[s1 * HIDDEN + j];
            float v2 = g_h1[s2 * HIDDEN + j];
            float v3 = g_h1[s3 * HIDDEN + j];
            float v4 = g_h1[s4 * HIDDEN + j];
            float v5 = g_h1[s5 * HIDDEN + j];
            float v6 = g_h1[s6 * HIDDEN + j];
            float v7 = g_h1[s7 * HIDDEN + j];
            acc += ((v0 + v1) + (v2 + v3)) + ((v4 + v5) + (v6 + v7));
        }
        for (; i < cnt; i++) {
            int s = __shfl_sync(mask, src, base + i);
            acc += g_h1[s * HIDDEN + j];
        }
        pos += cnt;
    }

    float dv = g_dinv[node];
    float y = fmaxf(dv * acc + sb1[j], 0.f);  // relu(agg + b1)

    #pragma unroll
    for (int c = 0; c < N_CLASSES; c++) {
        float t = y * sW2[j * N_CLASSES + c];
        t += __shfl_xor_sync(mask, t, 1);
        t += __shfl_xor_sync(mask, t, 2);
        t += __shfl_xor_sync(mask, t, 4);
        t += __shfl_xor_sync(mask, t, 8);
        if (j == c) g_y2[node * N_CLASSES + c] = dv * t;
    }
}

// ---------------- Layer-2 aggregation + bias + log_softmax ----------------
__global__ __launch_bounds__(256) void k_agg2(const float* __restrict__ b2,
                                              float* __restrict__ out) {
    int tid = threadIdx.x;
    int lane = tid & 31;
    int wid = tid >> 5;
    int sub = lane >> 3;            // 0..3
    int j = lane & 7;               // 0..7 (lane 7 inactive for data)
    int node = (blockIdx.x * 8 + wid) * 4 + sub;
    if (node >= N_NODES) return;
    unsigned mask = 0xFFu << (sub * 8);
    int base = sub * 8;
    int jr = (j < N_CLASSES) ? j : 0;

    float acc = (j < N_CLASSES) ? g_y2[node * N_CLASSES + j] : 0.f;
    int pos = g_rowptr[node];
    int end = g_rowptr[node + 1];
    while (pos < end) {
        int cnt = end - pos;
        if (cnt > 8) cnt = 8;
        int src = (j < cnt) ? g_adj[pos + j] : 0;
        int i = 0;
        for (; i + 4 <= cnt; i += 4) {
            int s0 = __shfl_sync(mask, src, base + i);
            int s1 = __shfl_sync(mask, src, base + i + 1);
            int s2 = __shfl_sync(mask, src, base + i + 2);
            int s3 = __shfl_sync(mask, src, base + i + 3);
            float v0 = g_y2[s0 * N_CLASSES + jr];
            float v1 = g_y2[s1 * N_CLASSES + jr];
            float v2 = g_y2[s2 * N_CLASSES + jr];
            float v3 = g_y2[s3 * N_CLASSES + jr];
            acc += (v0 + v1) + (v2 + v3);
        }
        for (; i < cnt; i++) {
            int s = __shfl_sync(mask, src, base + i);
            acc += g_y2[s * N_CLASSES + jr];
        }
        pos += cnt;
    }

    float dv = g_dinv[node];
    float o = dv * acc + ((j < N_CLASSES) ? __ldg(&b2[jr]) : 0.f);

    float m = (j < N_CLASSES) ? o : -1e30f;
    m = fmaxf(m, __shfl_xor_sync(mask, m, 1));
    m = fmaxf(m, __shfl_xor_sync(mask, m, 2));
    m = fmaxf(m, __shfl_xor_sync(mask, m, 4));
    float e = (j < N_CLASSES) ? expf(o - m) : 0.f;
    float s = e;
    s += __shfl_xor_sync(mask, s, 1);
    s += __shfl_xor_sync(mask, s, 2);
    s += __shfl_xor_sync(mask, s, 4);
    float ls = logf(s);
    if (j < N_CLASSES) out[node * N_CLASSES + j] = o - m - ls;
}

// ---------------- launch ----------------
extern "C" void kernel_launch(void* const* d_in, const int* in_sizes, int n_in,
                              void* d_out, int out_size) {
    const float* x  = (const float*)d_in[0];
    const int*   ei = (const int*)d_in[1];
    const float* W1 = (const float*)d_in[2];
    const float* b1 = (const float*)d_in[3];
    const float* W2 = (const float*)d_in[4];
    const float* b2 = (const float*)d_in[5];
    float* out = (float*)d_out;

    const int TB = 256;
    int gridN = (N_NODES + TB - 1) / TB;          // 391
    int gridE = (N_EDGES + TB - 1) / TB;
    int gridG = (N_NODES + TBM - 1) / TBM;        // 782
    int gridS = (N_NODES * HIDDEN / 4 + TB - 1) / TB;

    k_zero_deg<<<gridN, TB>>>();                  // 0
    k_count<<<gridE, TB>>>(ei);                   // 1
    k_s1<<<NBLK, 256>>>();                        // 2
    k_gemm1<<<gridG, 256>>>(x, W1);               // 3 <- profiled slot
    k_s3<<<NBLK, 256>>>();                        // 4
    k_fill<<<gridE, TB>>>(ei);                    // 5
    k_scale<<<gridS, TB>>>();                     // 6

    int grid1 = (N_NODES + 16 - 1) / 16;
    k_agg1<<<grid1, 256>>>(b1, W2);               // 7

    int grid2 = (N_NODES + 32 - 1) / 32;
    k_agg2<<<grid2, 256>>>(b2, out);              // 8
}